// round 5
// baseline (speedup 1.0000x reference)
#include <cuda_runtime.h>

// context_window: out[b, f*11 + c, t] = x[b, f, t + c - 5], zero-padded in t.
// x: (32, 80, 3000) fp32 -> out: (32, 880, 3000) fp32.
//
// R5: persistent grid-stride kernel. 912 resident CTAs (~6/SM) each loop over
// ~8.4 (row, t-chunk) work items, keeping warps resident and the store pipe
// continuously fed (R1-R4 used 7680 one-shot CTAs -> occupancy 47-61% and
// DRAM stuck at ~70%). Data path per item is the proven R1 layout:
// 5 aligned LDG.128 window loads -> 11 contiguous STG.128 streaming stores.

#define T_DIM     3000
#define C_LEN     11
#define ROWS      (32 * 80)       // 2560
#define T4        (T_DIM / 4)     // 750
#define CHUNK     256             // t4 values per work item
#define NCHUNK    3               // ceil(750/256)
#define NITEMS    (ROWS * NCHUNK) // 7680
#define GRID_X    912             // ~6 CTAs/SM on 152 SMs

__device__ __forceinline__ void stg_cs(float* p, float4 v) {
    asm volatile("st.global.cs.v4.f32 [%0], {%1, %2, %3, %4};"
                 :: "l"(p), "f"(v.x), "f"(v.y), "f"(v.z), "f"(v.w)
                 : "memory");
}

__global__ __launch_bounds__(CHUNK) void context_window_kernel(
    const float* __restrict__ x, float* __restrict__ out)
{
    for (int wi = blockIdx.x; wi < NITEMS; wi += GRID_X) {
        int row   = wi / NCHUNK;                    // b*80 + f
        int chunk = wi - row * NCHUNK;
        int t4    = chunk * CHUNK + threadIdx.x;
        if (t4 >= T4) continue;
        int t = t4 * 4;

        const float* __restrict__ xr = x + row * T_DIM;

        // Register window w[k] = x[t-8+k], k=0..19.
        // out[c, t+j] = x[t + j + c - 5] = w[j + c + 3]; used range w[3..16].
        float w[20];

        if (t4 >= 2 && t4 <= T4 - 3) {
            // Fast path: 5 aligned float4 loads, fully in-range.
            const float4* __restrict__ p =
                reinterpret_cast<const float4*>(xr + t - 8);
            #pragma unroll
            for (int i = 0; i < 5; i++) {
                float4 v = p[i];
                w[4*i + 0] = v.x; w[4*i + 1] = v.y;
                w[4*i + 2] = v.z; w[4*i + 3] = v.w;
            }
        } else {
            // Edge path (t4 in {0,1,748,749}): scalar bounds-checked loads.
            #pragma unroll
            for (int k = 0; k < 20; k++) {
                int idx = t - 8 + k;
                w[k] = (idx >= 0 && idx < T_DIM) ? xr[idx] : 0.0f;
            }
        }

        // 11 coalesced, aligned float4 streaming stores (warp-wide 512B each).
        float* __restrict__ orow = out + (row * C_LEN) * T_DIM + t;
        #pragma unroll
        for (int c = 0; c < C_LEN; c++) {
            stg_cs(orow + c * T_DIM,
                   make_float4(w[c + 3], w[c + 4], w[c + 5], w[c + 6]));
        }
    }
}

extern "C" void kernel_launch(void* const* d_in, const int* in_sizes, int n_in,
                              void* d_out, int out_size)
{
    const float* x = (const float*)d_in[0];
    float* out = (float*)d_out;

    context_window_kernel<<<GRID_X, CHUNK>>>(x, out);
}